// round 14
// baseline (speedup 1.0000x reference)
#include <cuda_runtime.h>

#define B_ 64
#define G_ 512
#define H_ 512
#define P_ 64
#define S_ 256
#define NPAIR 32               // b-pairs
#define HO_ 8                  // H split into 8 eighths of 64
#define NPROD (NPAIR * HO_)    // 256 producer blocks
#define NFILL (B_ * P_)        // 4096 consumer blocks
#define GRID_ (NPROD + NFILL)
#define TWO_PI_F 6.283185307179586f

// Split-K partials [h-eighth][b*64+p] + sync state. __device__ globals
// (allocation-free rule); zero-init at load, reset by last block per run.
__device__ float g_K1p[HO_][B_ * P_];
__device__ float g_K2p[HO_][B_ * P_];
__device__ int   g_pairdone[NPAIR];
__device__ int   g_finished;

// ---------------------------------------------------------------------------
// Fused kernel, grid 4352 x 256 threads.
//  bid <  256 : producer (bp = bid>>3, ho = bid&7): for both b's of pair bp,
//               x-slice (64 cols) of relu(Zg@Wl+bl), then 64-h partial heads.
//               ~2-3us each; all resident in wave 1.
//  bid >= 256 : consumer tile (b,p): waits ONLY on its pair's 8 producers
//               (per-pair flag — fixes R8's all-producer barrier), sums the
//               8 deterministic partials, then the frozen 86%-SOL fill body.
// ---------------------------------------------------------------------------
__global__ void __launch_bounds__(256, 8) fused_kernel(
    const float* __restrict__ Zg,  const float* __restrict__ phi,
    const float* __restrict__ Wl,  const float* __restrict__ bl,
    const float* __restrict__ W1,  const float* __restrict__ b1,
    const float* __restrict__ W2,  const float* __restrict__ b2,
    float* __restrict__ out)
{
    __shared__ __align__(16) char smraw[15360];
    const int t   = threadIdx.x;     // 0..255
    const int bid = blockIdx.x;

    if (bid < NPROD) {
        // ================= producer =================
        const int bp = bid >> 3;     // b-pair 0..31
        const int ho = bid & 7;      // h-eighth 0..7
        const int b0 = bp * 2;

        float*  zg  = (float*)smraw;                    // [2][512]   4KB
        float4* ps  = (float4*)(smraw + 4096);          // [2][16][16] 8KB
        float*  xh  = (float*)(smraw + 12288);          // [2][64]   512B
        float*  red = (float*)(smraw + 12800);          // [2][2][2][64] 2KB

        {   // load both b's inputs (float4, coalesced)
            const int bsel = t >> 7, idx = t & 127;
            ((float4*)(zg + bsel * G_))[idx] =
                ((const float4*)(Zg + (b0 + bsel) * G_))[idx];
        }
        __syncthreads();

        // ---- Stage 1: 64-col slice of x = relu(zg @ Wl + bl), both b's ----
        {
            const int c4 = t & 15;   // float4 col within slice (16 groups)
            const int gc = t >> 4;   // g-chunk 0..15 (32 g each)
            const float4* __restrict__ W4 = (const float4*)Wl;
            const int cidx = ho * 16 + c4;
            float4 a0 = make_float4(0.f, 0.f, 0.f, 0.f);
            float4 a1 = make_float4(0.f, 0.f, 0.f, 0.f);
            const int g0 = gc * 32;
#pragma unroll 8
            for (int g = g0; g < g0 + 32; ++g) {
                const float4 w  = W4[g * (H_ / 4) + cidx];  // LDG.128
                const float  z0 = zg[g];
                const float  z1 = zg[G_ + g];
                a0.x = fmaf(z0, w.x, a0.x);  a1.x = fmaf(z1, w.x, a1.x);
                a0.y = fmaf(z0, w.y, a0.y);  a1.y = fmaf(z1, w.y, a1.y);
                a0.z = fmaf(z0, w.z, a0.z);  a1.z = fmaf(z1, w.z, a1.z);
                a0.w = fmaf(z0, w.w, a0.w);  a1.w = fmaf(z1, w.w, a1.w);
            }
            ps[(0 * 16 + gc) * 16 + c4] = a0;
            ps[(1 * 16 + gc) * 16 + c4] = a1;
        }
        __syncthreads();

        if (t < 32) {                // reduce 16 g-chunks, bias, relu
            const int c4 = t & 15, bsel = t >> 4;
            float4 a = make_float4(0.f, 0.f, 0.f, 0.f);
#pragma unroll
            for (int gc = 0; gc < 16; ++gc) {
                const float4 v = ps[(bsel * 16 + gc) * 16 + c4];
                a.x += v.x; a.y += v.y; a.z += v.z; a.w += v.w;
            }
            const float4 bb = ((const float4*)bl)[ho * 16 + c4];
            a.x += bb.x; a.y += bb.y; a.z += bb.z; a.w += bb.w;
            a.x = a.x > 0.f ? a.x : 0.f;
            a.y = a.y > 0.f ? a.y : 0.f;
            a.z = a.z > 0.f ? a.z : 0.f;
            a.w = a.w > 0.f ? a.w : 0.f;
            ((float4*)(xh + bsel * 64))[c4] = a;
        }
        __syncthreads();

        // ---- Stage 2: 64-h partial heads, weights straight from gmem ----
        {
            const int p    = t & 63;
            const int head = (t >> 6) & 1;
            const int hc   = t >> 7;          // 0..1 (32-h subchunks)
            const float* __restrict__ W = head ? W2 : W1;
            const int hg0 = ho * 64 + hc * 32;
            const int hl0 = hc * 32;
            float k0 = 0.f, k1 = 0.f;
#pragma unroll 8
            for (int h = 0; h < 32; ++h) {
                const float w = W[(hg0 + h) * P_ + p];  // coalesced across p
                k0 = fmaf(xh[hl0 + h],      w, k0);
                k1 = fmaf(xh[64 + hl0 + h], w, k1);
            }
            red[((0 * 2 + head) * 2 + hc) * 64 + p] = k0;
            red[((1 * 2 + head) * 2 + hc) * 64 + p] = k1;
        }
        __syncthreads();

        {   // 256 threads = (bsel, head, p): combine + write partial
            const int p    = t & 63;
            const int head = (t >> 6) & 1;
            const int bsel = t >> 7;
            float k = red[((bsel * 2 + head) * 2 + 0) * 64 + p] +
                      red[((bsel * 2 + head) * 2 + 1) * 64 + p];
            if (ho == 0) k += head ? b2[p] : b1[p];   // bias once
            const int idx = (b0 + bsel) * P_ + p;
            if (head == 0) g_K1p[ho][idx] = k;
            else           g_K2p[ho][idx] = k;
        }
        // release: every thread fences its writes, then one arrival
        __threadfence();
        __syncthreads();
        if (t == 0) atomicAdd(&g_pairdone[bp], 1);
    } else {
        // ================= consumer: fill tile bp =================
        const int bp   = bid - NPROD;          // b*P + p
        const int pair = bp >> 7;              // (b>>1) = bp/(2*P_)
        float* sA = (float*)smraw;
        float* cA = sA + S_;
        float* sB = cA + S_;
        float* cB = sB + S_;

        if (t == 0) {                          // acquire (per-pair only)
            while (*(volatile int*)&g_pairdone[pair] < HO_) __nanosleep(64);
            __threadfence();
        }
        __syncthreads();

        const float K1 = ((g_K1p[0][bp] + g_K1p[1][bp]) +
                          (g_K1p[2][bp] + g_K1p[3][bp])) +
                         ((g_K1p[4][bp] + g_K1p[5][bp]) +
                          (g_K1p[6][bp] + g_K1p[7][bp]));
        const float K2 = ((g_K2p[0][bp] + g_K2p[1][bp]) +
                          (g_K2p[2][bp] + g_K2p[3][bp])) +
                         ((g_K2p[4][bp] + g_K2p[5][bp]) +
                          (g_K2p[6][bp] + g_K2p[7][bp]));
        const float ph = phi[bp] * TWO_PI_F;

        {
            float s, c;
            sincosf(K1 * (float)t, &s, &c);
            sA[t] = s; cA[t] = c;
            sincosf(K2 * (float)t + ph, &s, &c);
            sB[t] = s; cB[t] = c;
        }
        __syncthreads();

        const int    mi = t & 63;
        const int    r0 = t >> 6;
        const float4 sb = ((const float4*)sB)[mi];
        const float4 cb = ((const float4*)cB)[mi];
        float4* __restrict__ out4 = (float4*)(out + (size_t)bp * (S_ * S_));

#pragma unroll 8
        for (int i = 0; i < S_ / 4; ++i) {
            const int l  = (i << 2) + r0;
            const float sa = sA[l];
            const float ca = cA[l];
            float4 r;
            r.x = sa * cb.x + ca * sb.x;
            r.y = sa * cb.y + ca * sb.y;
            r.z = sa * cb.z + ca * sb.z;
            r.w = sa * cb.w + ca * sb.w;
            __stcs(&out4[l * (S_ / 4) + mi], r);  // streaming store
        }
    }

    // Replay-safe reset: last of all GRID_ blocks zeroes sync state.
    __syncthreads();
    if (t == 0) {
        __threadfence();
        const int f = atomicAdd(&g_finished, 1);
        if (f == GRID_ - 1) {
#pragma unroll
            for (int i = 0; i < NPAIR; ++i) g_pairdone[i] = 0;
            __threadfence();
            g_finished = 0;
        }
    }
}

extern "C" void kernel_launch(void* const* d_in, const int* in_sizes, int n_in,
                              void* d_out, int out_size) {
    const float* Zg  = (const float*)d_in[0];
    const float* phi = (const float*)d_in[1];
    const float* Wl  = (const float*)d_in[2];
    const float* bl  = (const float*)d_in[3];
    const float* W1  = (const float*)d_in[4];
    const float* b1  = (const float*)d_in[5];
    const float* W2  = (const float*)d_in[6];
    const float* b2  = (const float*)d_in[7];
    float* out = (float*)d_out;

    fused_kernel<<<GRID_, 256>>>(Zg, phi, Wl, bl, W1, b1, W2, b2, out);
}